// round 1
// baseline (speedup 1.0000x reference)
#include <cuda_runtime.h>
#include <cuda_bf16.h>

// Problem constants
#define BB 8
#define TT 20
#define CIN 64
#define HID 64
#define HH 64
#define WW 64
#define HWSZ 4096          // 64*64
#define CC 128             // CIN + HID
#define C4 256             // 4*HID
#define EPSBN 1e-5f

typedef unsigned long long ull;

// -------- persistent device state (allocation-free scratch) --------
__device__ float g_h[BB * HID * HWSZ];        // hidden state   (8.4 MB)
__device__ float g_c[BB * HID * HWSZ];        // cell state     (8.4 MB)
__device__ float g_dws[BB * CC * HWSZ];       // selu(bn1(dwconv(z)))  (16.8 MB)
__device__ float g_wp[128 * 256];             // folded pw weights, layout [k][j][gate]
__device__ float g_sp[256];                   // folded bn2 shift, layout [j][gate]
__device__ float g_dwf[CC * 9];               // folded dw weights
__device__ float g_dwb[CC];                   // folded bn1 shift

// -------- helpers --------
__device__ __forceinline__ ull pack2(float a, float b) {
    ull r;
    asm("mov.b64 %0, {%1,%2};" : "=l"(r) : "f"(a), "f"(b));
    return r;
}
__device__ __forceinline__ ull fma2(ull a, ull b, ull c) {
    ull d;
    asm("fma.rn.f32x2 %0, %1, %2, %3;" : "=l"(d) : "l"(a), "l"(b), "l"(c));
    return d;
}
__device__ __forceinline__ float unpk(ull v, int hi) {
    float lo, h;
    asm("mov.b64 {%0,%1}, %2;" : "=f"(lo), "=f"(h) : "l"(v));
    return hi ? h : lo;
}

__device__ __forceinline__ float selu_f(float x) {
    const float s = 1.0507009873554805f;
    const float sa = 1.7580993408473766f;   // s * alpha
    return x > 0.f ? s * x : sa * (__expf(x) - 1.f);
}
// sigmoid(selu(x))
__device__ __forceinline__ float gate_f(float x) {
    float u = selu_f(x);
    return __fdividef(1.f, 1.f + __expf(-u));
}
__device__ __forceinline__ float tanh_f(float x) {
    // 1 - 2/(e^{2x}+1): saturates correctly at +/-inf
    return 1.f - 2.f * __fdividef(1.f, __expf(2.f * x) + 1.f);
}

// -------- init: zero h and c --------
__global__ void init_kernel() {
    int i = blockIdx.x * blockDim.x + threadIdx.x;
    if (i < BB * HID * HWSZ) {
        g_h[i] = 0.f;
        g_c[i] = 0.f;
    }
}

// -------- prep: fold BN into conv weights, permute pw weights --------
__global__ void prep_kernel(const float* __restrict__ dw_w,
                            const float* __restrict__ g1, const float* __restrict__ b1,
                            const float* __restrict__ m1, const float* __restrict__ v1,
                            const float* __restrict__ pw,
                            const float* __restrict__ g2, const float* __restrict__ b2,
                            const float* __restrict__ m2, const float* __restrict__ v2) {
    int tid = threadIdx.x;   // 256 threads
    if (tid < CC) {
        float s = g1[tid] * rsqrtf(v1[tid] + EPSBN);
        #pragma unroll
        for (int k = 0; k < 9; k++) g_dwf[tid * 9 + k] = dw_w[tid * 9 + k] * s;
        g_dwb[tid] = b1[tid] - m1[tid] * s;
    }
    {
        int oc = tid;                       // 0..255
        float s = g2[oc] * rsqrtf(v2[oc] + EPSBN);
        int gate = oc >> 6;
        int j = oc & 63;
        g_sp[j * 4 + gate] = b2[oc] - m2[oc] * s;
        for (int k = 0; k < 128; k++)
            g_wp[k * 256 + j * 4 + gate] = pw[oc * 128 + k] * s;
    }
}

// -------- depthwise 3x3 + BN1 + SELU  (z = concat(x_t, h)) --------
__global__ void dw_kernel(const float* __restrict__ x, int t) {
    int idx = blockIdx.x * blockDim.x + threadIdx.x;   // 1,048,576 threads, 4 px each
    int w4 = idx & 15;
    int y  = (idx >> 4) & 63;
    int c  = (idx >> 10) & 127;
    int b  = idx >> 17;
    int x0 = w4 << 2;

    const float* src = (c < CIN)
        ? x + ((size_t)(b * TT + t) * CIN + c) * HWSZ
        : g_h + ((size_t)b * HID + (c - CIN)) * HWSZ;

    float r0[6], r1[6], r2[6];
    int ybase = y * WW;
    bool yt = (y > 0), yb = (y < HH - 1);
    #pragma unroll
    for (int dx = 0; dx < 6; dx++) {
        int xx = x0 - 1 + dx;
        bool xv = (xx >= 0) && (xx < WW);
        r0[dx] = (yt && xv) ? __ldg(src + ybase - WW + xx) : 0.f;
        r1[dx] = xv ? __ldg(src + ybase + xx) : 0.f;
        r2[dx] = (yb && xv) ? __ldg(src + ybase + WW + xx) : 0.f;
    }

    float w[9];
    #pragma unroll
    for (int i = 0; i < 9; i++) w[i] = __ldg(g_dwf + c * 9 + i);
    float bias = __ldg(g_dwb + c);

    float4 o;
    float* op = &o.x;
    #pragma unroll
    for (int p = 0; p < 4; p++) {
        float acc = bias;
        acc += w[0] * r0[p] + w[1] * r0[p + 1] + w[2] * r0[p + 2];
        acc += w[3] * r1[p] + w[4] * r1[p + 1] + w[5] * r1[p + 2];
        acc += w[6] * r2[p] + w[7] * r2[p + 1] + w[8] * r2[p + 2];
        op[p] = selu_f(acc);
    }
    *(float4*)(g_dws + ((size_t)(b * CC + c)) * HWSZ + ybase + x0) = o;
}

// -------- pointwise GEMM (f32x2) + BN2 + SELU + sigmoid + LSTM cell --------
// Block: one batch b, 128-pixel tile. 512 threads: thread = (j hidden-ch, g pixel-group).
// Thread owns 16 pixels (4 float4 segments at stride 32) x 4 gates of channel j.
__global__ void __launch_bounds__(512, 1)
pw_kernel(float* __restrict__ out, int t) {
    extern __shared__ float sm[];
    float* Ws = sm;                // 32768 floats: [k][j][gate]
    float* Bs = sm + 32768;        // 16384 floats: [k][128 px]

    int b  = blockIdx.x >> 5;
    int p0 = (blockIdx.x & 31) << 7;
    int tid = threadIdx.x;

    // stage weights (128 KB)
    {
        const float4* wp4 = (const float4*)g_wp;
        float4* Ws4 = (float4*)Ws;
        #pragma unroll
        for (int i = 0; i < 16; i++) Ws4[tid + i * 512] = wp4[tid + i * 512];
    }
    // stage activation tile (64 KB)
    {
        const float* dwsb = g_dws + (size_t)b * CC * HWSZ + p0;
        float4* Bs4 = (float4*)Bs;
        #pragma unroll
        for (int i = 0; i < 8; i++) {
            int idx = tid + i * 512;          // 0..4095 float4s
            int k = idx >> 5, pp = idx & 31;
            Bs4[idx] = *(const float4*)(dwsb + (size_t)k * HWSZ + pp * 4);
        }
    }
    __syncthreads();

    int j = tid >> 3;      // 0..63
    int g = tid & 7;       // 0..7

    ull acc[4][8];
    #pragma unroll
    for (int gt = 0; gt < 4; gt++)
        #pragma unroll
        for (int q = 0; q < 8; q++) acc[gt][q] = 0ULL;

    const float4* WsJ = (const float4*)Ws + j;          // + k*64
    const ulonglong2* Bu = (const ulonglong2*)Bs + g;   // + k*32 + i*8

    #pragma unroll 2
    for (int k = 0; k < 128; k++) {
        float4 w = WsJ[k * 64];
        ull wi = pack2(w.x, w.x);
        ull wf = pack2(w.y, w.y);
        ull wo = pack2(w.z, w.z);
        ull wg = pack2(w.w, w.w);
        #pragma unroll
        for (int i = 0; i < 4; i++) {
            ulonglong2 bv = Bu[k * 32 + i * 8];
            acc[0][2 * i    ] = fma2(wi, bv.x, acc[0][2 * i    ]);
            acc[0][2 * i + 1] = fma2(wi, bv.y, acc[0][2 * i + 1]);
            acc[1][2 * i    ] = fma2(wf, bv.x, acc[1][2 * i    ]);
            acc[1][2 * i + 1] = fma2(wf, bv.y, acc[1][2 * i + 1]);
            acc[2][2 * i    ] = fma2(wo, bv.x, acc[2][2 * i    ]);
            acc[2][2 * i + 1] = fma2(wo, bv.y, acc[2][2 * i + 1]);
            acc[3][2 * i    ] = fma2(wg, bv.x, acc[3][2 * i    ]);
            acc[3][2 * i + 1] = fma2(wg, bv.y, acc[3][2 * i + 1]);
        }
    }

    // epilogue: BN2 shift + selu + sigmoid -> gates; cell update; tanh; writes
    float4 sh = ((const float4*)g_sp)[j];
    size_t plane = ((size_t)b * HID + j) * HWSZ + p0;
    float* hb = g_h + plane;
    float* cb = g_c + plane;
    float* ob = out + ((size_t)(b * TT + t) * HID + j) * HWSZ + p0;

    #pragma unroll
    for (int i = 0; i < 4; i++) {
        int off = i * 32 + g * 4;
        float4 co = *(float4*)(cb + off);
        float4 cn, hn;
        const float* cop = &co.x;
        float* cnp = &cn.x;
        float* hnp = &hn.x;
        #pragma unroll
        for (int p = 0; p < 4; p++) {
            int q = 2 * i + (p >> 1);
            int hi = p & 1;
            float zi = unpk(acc[0][q], hi) + sh.x;
            float zf = unpk(acc[1][q], hi) + sh.y;
            float zo = unpk(acc[2][q], hi) + sh.z;
            float zg = unpk(acc[3][q], hi) + sh.w;
            float gi = gate_f(zi);
            float gf = gate_f(zf);
            float go = gate_f(zo);
            float gg = gate_f(zg);
            float cv = gf * cop[p] + gi * gg;
            cnp[p] = cv;
            hnp[p] = go * tanh_f(cv);
        }
        *(float4*)(cb + off) = cn;
        *(float4*)(hb + off) = hn;
        *(float4*)(ob + off) = hn;
    }
}

// -------- launch --------
extern "C" void kernel_launch(void* const* d_in, const int* in_sizes, int n_in,
                              void* d_out, int out_size) {
    const float* x      = (const float*)d_in[0];
    const float* dw_w   = (const float*)d_in[1];
    const float* gamma1 = (const float*)d_in[2];
    const float* beta1  = (const float*)d_in[3];
    const float* mean1  = (const float*)d_in[4];
    const float* var1   = (const float*)d_in[5];
    const float* pw_w   = (const float*)d_in[6];
    const float* gamma2 = (const float*)d_in[7];
    const float* beta2  = (const float*)d_in[8];
    const float* mean2  = (const float*)d_in[9];
    const float* var2   = (const float*)d_in[10];
    float* out = (float*)d_out;

    cudaFuncSetAttribute(pw_kernel, cudaFuncAttributeMaxDynamicSharedMemorySize, 196608);

    init_kernel<<<(BB * HID * HWSZ + 511) / 512, 512>>>();
    prep_kernel<<<1, 256>>>(dw_w, gamma1, beta1, mean1, var1,
                            pw_w, gamma2, beta2, mean2, var2);

    for (int t = 0; t < TT; t++) {
        dw_kernel<<<4096, 256>>>(x, t);
        pw_kernel<<<256, 512, 196608>>>(out, t);
    }
}